// round 14
// baseline (speedup 1.0000x reference)
#include <cuda_runtime.h>
#include <cuda_bf16.h>
#include <cuda_fp16.h>
#include <math.h>
#include <stdint.h>

#define T_SEQ   1536
#define DMODEL  2880
#define QKVD    5120
#define NH      64
#define NKV     8
#define HD      64
#define WIN     128
#define NEG_INF -1e30f
#define N2PAD   2944

// int8 quantization scales (GEMM1): x = dx*(128*a1+a0), W = dw*(128*b1+b0)
#define XRANGE  6.0f
#define WRANGE  0.14f
#define QLEVELS 16256.0f
#define INV_DX  (QLEVELS / XRANGE)
#define INV_DW  (QLEVELS / WRANGE)
#define C1_SCALE ((float)((double)XRANGE * (double)WRANGE / ((double)QLEVELS * (double)QLEVELS) * 16384.0))
#define C2_SCALE ((float)((double)XRANGE * (double)WRANGE / ((double)QLEVELS * (double)QLEVELS) * 128.0))

// ---------------------------------------------------------------------------
// scratch
// ---------------------------------------------------------------------------
__device__ __align__(16) float g_qkv[T_SEQ * QKVD];
__device__ __align__(16) signed char g_xq1[T_SEQ * DMODEL];
__device__ __align__(16) signed char g_xq0[T_SEQ * DMODEL];
__device__ __align__(16) signed char g_w1q1[QKVD * DMODEL];       // [N=5120, K=2880]
__device__ __align__(16) signed char g_w1q0[QKVD * DMODEL];
__device__ __align__(16) __nv_bfloat16 g_w2hi[N2PAD * (NH * HD)]; // [N, K=4096]
__device__ __align__(16) __nv_bfloat16 g_w2lo[N2PAD * (NH * HD)];
__device__ __align__(16) __nv_bfloat16 g_ahi[T_SEQ * NH * HD];
__device__ __align__(16) __nv_bfloat16 g_alo[T_SEQ * NH * HD];
__device__ float g_invf[32];
__device__ float g_conc;

// ---------------------------------------------------------------------------
// PTX helpers (family-generic sm_80+ only)
// ---------------------------------------------------------------------------
__device__ __forceinline__ uint32_t smem_u32(const void* p) {
    uint32_t a;
    asm("{ .reg .u64 t; cvta.to.shared.u64 t, %1; cvt.u32.u64 %0, t; }" : "=r"(a) : "l"(p));
    return a;
}
#define CP_ASYNC16(dst, src) \
    asm volatile("cp.async.cg.shared.global [%0], [%1], 16;" :: "r"(dst), "l"(src))
#define CP_COMMIT() asm volatile("cp.async.commit_group;" ::: "memory")
#define CP_WAIT(n)  asm volatile("cp.async.wait_group %0;" :: "n"(n) : "memory")
#define LDSM4(r0, r1, r2, r3, addr) \
    asm volatile("ldmatrix.sync.aligned.m8n8.x4.shared.b16 {%0,%1,%2,%3}, [%4];" \
        : "=r"(r0), "=r"(r1), "=r"(r2), "=r"(r3) : "r"(addr))
#define LDSM4T(r0, r1, r2, r3, addr) \
    asm volatile("ldmatrix.sync.aligned.m8n8.x4.trans.shared.b16 {%0,%1,%2,%3}, [%4];" \
        : "=r"(r0), "=r"(r1), "=r"(r2), "=r"(r3) : "r"(addr))
#define MMA16816(d, a, b) \
    asm volatile("mma.sync.aligned.m16n8k16.row.col.f32.bf16.bf16.f32 " \
        "{%0,%1,%2,%3}, {%4,%5,%6,%7}, {%8,%9}, {%0,%1,%2,%3};" \
        : "+f"((d)[0]), "+f"((d)[1]), "+f"((d)[2]), "+f"((d)[3]) \
        : "r"((a)[0]), "r"((a)[1]), "r"((a)[2]), "r"((a)[3]), "r"((b)[0]), "r"((b)[1]))
#define MMAH(d, a, b) \
    asm volatile("mma.sync.aligned.m16n8k16.row.col.f32.f16.f16.f32 " \
        "{%0,%1,%2,%3}, {%4,%5,%6,%7}, {%8,%9}, {%0,%1,%2,%3};" \
        : "+f"((d)[0]), "+f"((d)[1]), "+f"((d)[2]), "+f"((d)[3]) \
        : "r"((a)[0]), "r"((a)[1]), "r"((a)[2]), "r"((a)[3]), "r"((b)[0]), "r"((b)[1]))
#define MMAI8(d, a, b) \
    asm volatile("mma.sync.aligned.m16n8k32.row.col.s32.s8.s8.s32 " \
        "{%0,%1,%2,%3}, {%4,%5,%6,%7}, {%8,%9}, {%0,%1,%2,%3};" \
        : "+r"((d)[0]), "+r"((d)[1]), "+r"((d)[2]), "+r"((d)[3]) \
        : "r"((a)[0]), "r"((a)[1]), "r"((a)[2]), "r"((a)[3]), "r"((b)[0]), "r"((b)[1]))

__device__ __forceinline__ uint32_t pack_h2(float a, float b) {
    __half2 h = __floats2half2_rn(a, b);
    return *(uint32_t*)&h;
}

// smem geometry shared by both GEMMs: 4 tiles/stage, 128 rows x 80B pitch (64B data)
#define ROW_B   80
#define TILE_B  (128 * ROW_B)          // 10240
#define STAGE_B (4 * TILE_B)           // 40960
#define GEMM_SMEM (2 * STAGE_B)        // 81920

// ---------------------------------------------------------------------------
// IMMA 2-digit int8 GEMM (GEMM1): C = dx*dw*(16384*A1B1 + 128*(A1B0+A0B1)) + bias
// 512 thr, 16 warps (4x4), warp tile 32x32, K-chunk 64, 2-stage cp.async.
// A digits [M,K] s8, B digits [N,K] s8. M%128==0, N%128==0, K%64==0.
// ---------------------------------------------------------------------------
__global__ __launch_bounds__(512, 1)
void gemm_imma(int M, int N, int K,
               const signed char* __restrict__ Aq1, const signed char* __restrict__ Aq0,
               const signed char* __restrict__ Bq1, const signed char* __restrict__ Bq0,
               const float* __restrict__ bias, float* __restrict__ C)
{
    extern __shared__ char smem[];
    const uint32_t sb = smem_u32(smem);
    const int tid = threadIdx.x;
    const int wid = tid >> 5, lane = tid & 31;
    const int wm = wid & 3, wn = wid >> 2;          // 4 x 4 warp grid
    const int bm = blockIdx.y * 128, bn = blockIdx.x * 128;

    // loader: thread = one 16B unit per tile (128 rows x 4 chunks = 512 units)
    const int ld_row = tid >> 2;
    const int ld_c16 = tid & 3;
    const uint32_t ld_dst = sb + ld_row * ROW_B + ld_c16 * 16;
    const size_t a_goff = (size_t)(bm + ld_row) * K + ld_c16 * 16;
    const size_t b_goff = (size_t)(bn + ld_row) * K + ld_c16 * 16;

    // fragment addressing (s8 tiles via b16 ldmatrix: layouts coincide)
    const int a_row = wm * 32 + (lane & 15);
    const int a_c   = (lane >> 4) * 16;
    const int b_row = wn * 32 + (lane & 7) + ((lane >> 4) & 1) * 8;
    const int b_c   = ((lane >> 3) & 1) * 16;

    int acc1[2][4][4], accx[2][4][4];
    #pragma unroll
    for (int mt = 0; mt < 2; mt++)
        #pragma unroll
        for (int nt = 0; nt < 4; nt++)
            #pragma unroll
            for (int r = 0; r < 4; r++) { acc1[mt][nt][r] = 0; accx[mt][nt][r] = 0; }

    const int nch = K >> 6;

    auto load_stage = [&](int s, int c) {
        const uint32_t d0 = ld_dst + s * STAGE_B;
        const int kc = c * 64;
        CP_ASYNC16(d0 + 0 * TILE_B, Aq1 + a_goff + kc);
        CP_ASYNC16(d0 + 1 * TILE_B, Aq0 + a_goff + kc);
        CP_ASYNC16(d0 + 2 * TILE_B, Bq1 + b_goff + kc);
        CP_ASYNC16(d0 + 3 * TILE_B, Bq0 + b_goff + kc);
    };

    load_stage(0, 0);
    CP_COMMIT();

    for (int c = 0; c < nch; c++) {
        const int s = c & 1;
        CP_WAIT(0);
        __syncthreads();
        if (c + 1 < nch) {
            load_stage(s ^ 1, c + 1);
            CP_COMMIT();
        }

        const uint32_t stg = sb + s * STAGE_B;
        #pragma unroll
        for (int kk = 0; kk < 2; kk++) {
            uint32_t bh[4][2], bl[4][2];
            #pragma unroll
            for (int bp = 0; bp < 2; bp++) {
                const uint32_t rb = stg + 2 * TILE_B + (b_row + bp * 16) * ROW_B + kk * 32 + b_c;
                LDSM4(bh[bp*2][0], bh[bp*2][1], bh[bp*2+1][0], bh[bp*2+1][1], rb);
                LDSM4(bl[bp*2][0], bl[bp*2][1], bl[bp*2+1][0], bl[bp*2+1][1], rb + TILE_B);
            }
            #pragma unroll
            for (int mt = 0; mt < 2; mt++) {
                uint32_t a1[4], a0[4];
                const uint32_t ra = stg + (a_row + mt * 16) * ROW_B + kk * 32 + a_c;
                LDSM4(a1[0], a1[1], a1[2], a1[3], ra);
                LDSM4(a0[0], a0[1], a0[2], a0[3], ra + TILE_B);
                #pragma unroll
                for (int nt = 0; nt < 4; nt++) MMAI8(acc1[mt][nt], a1, bh[nt]);
                #pragma unroll
                for (int nt = 0; nt < 4; nt++) MMAI8(accx[mt][nt], a1, bl[nt]);
                #pragma unroll
                for (int nt = 0; nt < 4; nt++) MMAI8(accx[mt][nt], a0, bh[nt]);
            }
        }
    }

    // epilogue: combine digit products, add bias, store fp32
    const int r_base = bm + wm * 32 + (lane >> 2);
    const int c_base = bn + wn * 32 + (lane & 3) * 2;
    #pragma unroll
    for (int mt = 0; mt < 2; mt++) {
        #pragma unroll
        for (int nt = 0; nt < 4; nt++) {
            const int cc = c_base + nt * 8;
            const float2 bs = *(const float2*)&bias[cc];
            const int r0 = r_base + mt * 16;
            float2 v0, v1;
            v0.x = (float)acc1[mt][nt][0] * C1_SCALE + (float)accx[mt][nt][0] * C2_SCALE + bs.x;
            v0.y = (float)acc1[mt][nt][1] * C1_SCALE + (float)accx[mt][nt][1] * C2_SCALE + bs.y;
            v1.x = (float)acc1[mt][nt][2] * C1_SCALE + (float)accx[mt][nt][2] * C2_SCALE + bs.x;
            v1.y = (float)acc1[mt][nt][3] * C1_SCALE + (float)accx[mt][nt][3] * C2_SCALE + bs.y;
            *(float2*)&C[(size_t)r0 * N + cc]       = v0;
            *(float2*)&C[(size_t)(r0 + 8) * N + cc] = v1;
        }
    }
}

// ---------------------------------------------------------------------------
// HMMA bf16-split GEMM (GEMM2, frozen since R6)
// ---------------------------------------------------------------------------
template <int GUARD_N>
__global__ __launch_bounds__(256, 2)
void gemm_hmma(int M, int N, int K,
               const __nv_bfloat16* __restrict__ Ahi, const __nv_bfloat16* __restrict__ Alo,
               const __nv_bfloat16* __restrict__ Bhi, const __nv_bfloat16* __restrict__ Blo,
               const float* __restrict__ bias, float* __restrict__ C)
{
    extern __shared__ char smem[];
    const uint32_t sb = smem_u32(smem);
    const int tid = threadIdx.x;
    const int wid = tid >> 5, lane = tid & 31;
    const int wm = wid & 1, wn = wid >> 1;          // 2 x 4 warp grid
    const int bm = blockIdx.y * 128, bn = blockIdx.x * 128;

    const int ld_row = tid >> 2;
    const int ld_c16 = tid & 3;
    const uint32_t ld_dst = sb + ld_row * ROW_B + ld_c16 * 16;
    const size_t a_off0 = (size_t)(bm + ld_row) * K + ld_c16 * 8;
    const size_t a_off1 = (size_t)(bm + ld_row + 64) * K + ld_c16 * 8;
    const size_t b_off0 = (size_t)(bn + ld_row) * K + ld_c16 * 8;
    const size_t b_off1 = (size_t)(bn + ld_row + 64) * K + ld_c16 * 8;

    const int a_row  = wm * 64 + (lane & 7) + (lane & 8);
    const int a_koff = ((lane >> 4) & 1) * 16;
    const int b_row  = wn * 32 + (lane & 7) + ((lane >> 4) & 1) * 8;
    const int b_koff = ((lane >> 3) & 1) * 16;

    float acc[4][4][4];
    #pragma unroll
    for (int i = 0; i < 4; i++)
        #pragma unroll
        for (int j = 0; j < 4; j++)
            #pragma unroll
            for (int r = 0; r < 4; r++) acc[i][j][r] = 0.0f;

    const int nch = K >> 5;

    auto load_stage = [&](int s, int c) {
        const uint32_t d0 = ld_dst + s * STAGE_B;
        const int kc = c * 32;
        CP_ASYNC16(d0 + 0 * TILE_B,              Ahi + a_off0 + kc);
        CP_ASYNC16(d0 + 0 * TILE_B + 64 * ROW_B, Ahi + a_off1 + kc);
        CP_ASYNC16(d0 + 1 * TILE_B,              Alo + a_off0 + kc);
        CP_ASYNC16(d0 + 1 * TILE_B + 64 * ROW_B, Alo + a_off1 + kc);
        CP_ASYNC16(d0 + 2 * TILE_B,              Bhi + b_off0 + kc);
        CP_ASYNC16(d0 + 2 * TILE_B + 64 * ROW_B, Bhi + b_off1 + kc);
        CP_ASYNC16(d0 + 3 * TILE_B,              Blo + b_off0 + kc);
        CP_ASYNC16(d0 + 3 * TILE_B + 64 * ROW_B, Blo + b_off1 + kc);
    };

    load_stage(0, 0);
    CP_COMMIT();

    for (int c = 0; c < nch; c++) {
        const int s = c & 1;
        CP_WAIT(0);
        __syncthreads();
        if (c + 1 < nch) {
            load_stage(s ^ 1, c + 1);
            CP_COMMIT();
        }

        const uint32_t stg = sb + s * STAGE_B;
        #pragma unroll
        for (int kk = 0; kk < 2; kk++) {
            const uint32_t a_k = a_koff + kk * 32;
            const uint32_t b_k = b_koff + kk * 32;
            uint32_t bh[4][2], bl[4][2];
            #pragma unroll
            for (int bp = 0; bp < 2; bp++) {
                const uint32_t rb = stg + 2 * TILE_B + (b_row + bp * 16) * ROW_B + b_k;
                LDSM4(bh[bp*2][0], bh[bp*2][1], bh[bp*2+1][0], bh[bp*2+1][1], rb);
                LDSM4(bl[bp*2][0], bl[bp*2][1], bl[bp*2+1][0], bl[bp*2+1][1], rb + TILE_B);
            }
            #pragma unroll
            for (int tm = 0; tm < 4; tm++) {
                uint32_t ah[4], al[4];
                const uint32_t ra = stg + (a_row + tm * 16) * ROW_B + a_k;
                LDSM4(ah[0], ah[1], ah[2], ah[3], ra);
                LDSM4(al[0], al[1], al[2], al[3], ra + TILE_B);
                #pragma unroll
                for (int tn = 0; tn < 4; tn++) MMA16816(acc[tm][tn], ah, bh[tn]);
                #pragma unroll
                for (int tn = 0; tn < 4; tn++) MMA16816(acc[tm][tn], ah, bl[tn]);
                #pragma unroll
                for (int tn = 0; tn < 4; tn++) MMA16816(acc[tm][tn], al, bh[tn]);
            }
        }
    }

    const int r_base = bm + wm * 64 + (lane >> 2);
    const int c_base = bn + wn * 32 + (lane & 3) * 2;
    #pragma unroll
    for (int tm = 0; tm < 4; tm++) {
        #pragma unroll
        for (int tn = 0; tn < 4; tn++) {
            const int cc = c_base + tn * 8;
            if (GUARD_N && cc >= N) continue;
            const float2 bs = *(const float2*)&bias[cc];
            const int r0 = r_base + tm * 16;
            float2 v0, v1;
            v0.x = acc[tm][tn][0] + bs.x; v0.y = acc[tm][tn][1] + bs.y;
            v1.x = acc[tm][tn][2] + bs.x; v1.y = acc[tm][tn][3] + bs.y;
            *(float2*)&C[(size_t)r0 * N + cc]       = v0;
            *(float2*)&C[(size_t)(r0 + 8) * N + cc] = v1;
        }
    }
}

// ---------------------------------------------------------------------------
// fp32 -> 2-digit s8 quantization (elementwise, for x)
// ---------------------------------------------------------------------------
__global__ void quant8(const float* __restrict__ in,
                       signed char* __restrict__ hi, signed char* __restrict__ lo,
                       int n, float invd)
{
    int i = blockIdx.x * blockDim.x + threadIdx.x;
    if (i >= n) return;
    const float f = fminf(fmaxf(in[i] * invd, -QLEVELS), QLEVELS);
    const int q = __float2int_rn(f);
    const int h = (q + 64) >> 7;
    hi[i] = (signed char)h;
    lo[i] = (signed char)(q - (h << 7));
}

// ---------------------------------------------------------------------------
// W [K,N] fp32 -> 2-digit s8 [N,K] (transpose + quantize)
// ---------------------------------------------------------------------------
__global__ void transpose_quant8(int K, int N, const float* __restrict__ W,
                                 signed char* __restrict__ Thi,
                                 signed char* __restrict__ Tlo, float invd)
{
    __shared__ float tile[32][33];
    const int k0 = blockIdx.y * 32, n0 = blockIdx.x * 32;
    const int tx = threadIdx.x, ty = threadIdx.y;
    #pragma unroll
    for (int i = 0; i < 32; i += 8)
        tile[ty + i][tx] = W[(size_t)(k0 + ty + i) * N + n0 + tx];
    __syncthreads();
    #pragma unroll
    for (int i = 0; i < 32; i += 8) {
        const int n = n0 + ty + i;
        const float f = fminf(fmaxf(tile[tx][ty + i] * invd, -QLEVELS), QLEVELS);
        const int q = __float2int_rn(f);
        const int h = (q + 64) >> 7;
        Thi[(size_t)n * K + k0 + tx] = (signed char)h;
        Tlo[(size_t)n * K + k0 + tx] = (signed char)(q - (h << 7));
    }
}

// ---------------------------------------------------------------------------
// W [K,N] fp32 -> Thi/Tlo [Npad,K] bf16 (GEMM2 weights)
// ---------------------------------------------------------------------------
__global__ void transpose_convert(int K, int N, const float* __restrict__ W,
                                  __nv_bfloat16* __restrict__ Thi,
                                  __nv_bfloat16* __restrict__ Tlo)
{
    __shared__ float tile[32][33];
    const int k0 = blockIdx.y * 32, n0 = blockIdx.x * 32;
    const int tx = threadIdx.x, ty = threadIdx.y;
    #pragma unroll
    for (int i = 0; i < 32; i += 8) {
        const int k = k0 + ty + i;
        tile[ty + i][tx] = (n0 + tx < N) ? W[(size_t)k * N + n0 + tx] : 0.0f;
    }
    __syncthreads();
    #pragma unroll
    for (int i = 0; i < 32; i += 8) {
        const int n = n0 + ty + i;
        const float v = (n < N) ? tile[tx][ty + i] : 0.0f;
        const __nv_bfloat16 h = __float2bfloat16(v);
        Thi[(size_t)n * K + k0 + tx] = h;
        Tlo[(size_t)n * K + k0 + tx] = __float2bfloat16(v - __bfloat162float(h));
    }
}

// ---------------------------------------------------------------------------
// YaRN RoPE
// ---------------------------------------------------------------------------
__global__ void rope_init()
{
    const int i = threadIdx.x;
    const double TWO_PI = 6.283185307179586;
    double freq = pow(150000.0, (double)(2 * i) / 64.0);
    double conc = 0.1 * log(32.0) + 1.0;
    double lo   = 32.0 * log(1024.0 / (32.0 * TWO_PI)) / log(150000.0);
    double hi   = 32.0 * log(1024.0 / TWO_PI) / log(150000.0);
    double ramp = ((double)i - lo) / (hi - lo);
    ramp = fmin(1.0, fmax(0.0, ramp));
    g_invf[i] = (float)(ramp / (32.0 * freq) + (1.0 - ramp) / freq);
    if (i == 0) g_conc = (float)conc;
}

__global__ void rope_kernel(float* __restrict__ qkv)
{
    const int gid = blockIdx.x * blockDim.x + threadIdx.x;
    const int i   = gid & 31;
    const int hh  = (gid >> 5) % 72;
    const int t   = gid / (32 * 72);
    if (t >= T_SEQ) return;

    const float ang = (float)t * g_invf[i];
    const float cc  = g_conc;
    const float c   = cosf(ang) * cc;
    const float s   = sinf(ang) * cc;

    const int col = (hh < 64) ? hh * 64 : 4096 + (hh - 64) * 64;
    float* p = qkv + (size_t)t * QKVD + col;
    const float x1 = p[i];
    const float x2 = p[i + 32];
    p[i]      = x1 * c - x2 * s;
    p[i + 32] = x2 * c + x1 * s;
}

// ---------------------------------------------------------------------------
// Tensor-core flash attention (proven in R12)
// ---------------------------------------------------------------------------
#define QB      32
#define KW      160
#define NSTRIP  10
#define APITCH  72
#define Q_BYTES (8 * QB * APITCH * 2)
#define K_BYTES (KW * APITCH * 2)
#define AOFF_QHI 0
#define AOFF_QLO (AOFF_QHI + Q_BYTES)
#define AOFF_KHI (AOFF_QLO + Q_BYTES)
#define AOFF_KLO (AOFF_KHI + K_BYTES)
#define AOFF_VH  (AOFF_KLO + K_BYTES)
#define ATTN_SMEM (AOFF_VH + K_BYTES)

__global__ __launch_bounds__(256)
void attn_mma(const float* __restrict__ qkv, const float* __restrict__ sinks,
              __nv_bfloat16* __restrict__ ahi, __nv_bfloat16* __restrict__ alo)
{
    extern __shared__ char smem[];
    const uint32_t sb = smem_u32(smem);
    const int tid = threadIdx.x, lane = tid & 31, w = tid >> 5;
    const int qb = blockIdx.x, hkv = blockIdx.y;
    const int q0 = qb * QB;
    const int kbase = q0 - 128;

    __half* qh = (__half*)(smem + AOFF_QHI);
    __half* ql = (__half*)(smem + AOFF_QLO);
    __half* kh = (__half*)(smem + AOFF_KHI);
    __half* kl = (__half*)(smem + AOFF_KLO);
    __half* vh = (__half*)(smem + AOFF_VH);

    for (int idx = tid; idx < QB * 128; idx += 256) {
        const int q = idx >> 7, c4 = (idx & 127) << 2;
        const float4 v = *(const float4*)(qkv + (size_t)(q0 + q) * QKVD + hkv * 512 + c4);
        const int head = c4 >> 6, d = c4 & 63;
        __half* ph = qh + head * (QB * APITCH) + q * APITCH + d;
        __half* pl = ql + head * (QB * APITCH) + q * APITCH + d;
        const float a[4] = {v.x * 0.125f, v.y * 0.125f, v.z * 0.125f, v.w * 0.125f};
        #pragma unroll
        for (int t = 0; t < 4; t++) {
            const __half h = __float2half_rn(a[t]);
            ph[t] = h;
            pl[t] = __float2half_rn(a[t] - __half2float(h));
        }
    }
    for (int idx = tid; idx < KW * 16; idx += 256) {
        const int k = idx >> 4, c4 = (idx & 15) << 2;
        const int j = kbase + k;
        float4 kv = make_float4(0.f, 0.f, 0.f, 0.f);
        float4 vv = make_float4(0.f, 0.f, 0.f, 0.f);
        if (j >= 0) {
            kv = *(const float4*)(qkv + (size_t)j * QKVD + 4096 + hkv * 64 + c4);
            vv = *(const float4*)(qkv + (size_t)j * QKVD + 4608 + hkv * 64 + c4);
        }
        __half* pkh = kh + k * APITCH + c4;
        __half* pkl = kl + k * APITCH + c4;
        __half* pvh = vh + k * APITCH + c4;
        const float ka[4] = {kv.x, kv.y, kv.z, kv.w};
        const float va[4] = {vv.x, vv.y, vv.z, vv.w};
        #pragma unroll
        for (int t = 0; t < 4; t++) {
            const __half h = __float2half_rn(ka[t]);
            pkh[t] = h;
            pkl[t] = __float2half_rn(ka[t] - __half2float(h));
            pvh[t] = __float2half_rn(va[t]);
        }
    }
    __syncthreads();

    const uint32_t qhi_base = sb + AOFF_QHI + w * (QB * APITCH * 2);
    const uint32_t qlo_base = sb + AOFF_QLO + w * (QB * APITCH * 2);
    const uint32_t khi_base = sb + AOFF_KHI;
    const uint32_t klo_base = sb + AOFF_KLO;
    const uint32_t vh_base  = sb + AOFF_VH;

    const uint32_t a_off = ((lane & 15) * APITCH + (lane >> 4) * 8) * 2;
    const uint32_t k_off = (((lane & 7) + (lane >> 4) * 8) * APITCH + ((lane >> 3) & 1) * 8) * 2;
    const uint32_t v_off = (((lane & 7) + ((lane >> 3) & 1) * 8) * APITCH + (lane >> 4) * 8) * 2;

    float O[2][8][4];
    #pragma unroll
    for (int mt = 0; mt < 2; mt++)
        #pragma unroll
        for (int dn = 0; dn < 8; dn++)
            #pragma unroll
            for (int c = 0; c < 4; c++) O[mt][dn][c] = 0.0f;
    float Mx[2][2], Ls[2][2];
    #pragma unroll
    for (int mt = 0; mt < 2; mt++) { Mx[mt][0] = Mx[mt][1] = -50.0f; Ls[mt][0] = Ls[mt][1] = 0.0f; }

    const int row_l = lane >> 2;
    const int col_l = (lane & 3) << 1;

    int s0 = 0;
    if (kbase < 0) s0 = (-kbase) >> 4;

    for (int s = s0; s < NSTRIP; s++) {
        const int kg0 = kbase + s * 16;
        float S[2][2][4];
        #pragma unroll
        for (int mt = 0; mt < 2; mt++)
            #pragma unroll
            for (int nt = 0; nt < 2; nt++)
                #pragma unroll
                for (int c = 0; c < 4; c++) S[mt][nt][c] = 0.0f;

        #pragma unroll
        for (int kt = 0; kt < 4; kt++) {
            uint32_t kbh[4], kbl[4];
            const uint32_t rk = (s * 16 * APITCH + kt * 16) * 2;
            LDSM4(kbh[0], kbh[1], kbh[2], kbh[3], khi_base + rk + k_off);
            LDSM4(kbl[0], kbl[1], kbl[2], kbl[3], klo_base + rk + k_off);
            #pragma unroll
            for (int mt = 0; mt < 2; mt++) {
                uint32_t ah[4], al[4];
                const uint32_t rq = (mt * 16 * APITCH + kt * 16) * 2;
                LDSM4(ah[0], ah[1], ah[2], ah[3], qhi_base + rq + a_off);
                LDSM4(al[0], al[1], al[2], al[3], qlo_base + rq + a_off);
                #pragma unroll
                for (int nt = 0; nt < 2; nt++) {
                    MMAH(S[mt][nt], ah, kbh + nt * 2);
                    MMAH(S[mt][nt], ah, kbl + nt * 2);
                    MMAH(S[mt][nt], al, kbh + nt * 2);
                }
            }
        }

        #pragma unroll
        for (int mt = 0; mt < 2; mt++)
            #pragma unroll
            for (int nt = 0; nt < 2; nt++)
                #pragma unroll
                for (int c = 0; c < 4; c++) {
                    const int i = q0 + mt * 16 + row_l + ((c >> 1) << 3);
                    const int j = kg0 + nt * 8 + col_l + (c & 1);
                    const bool ok = (j >= 0) && (j <= i) && (j > i - WIN);
                    if (!ok) S[mt][nt][c] = NEG_INF;
                }

        uint32_t pa[2][4];
        #pragma unroll
        for (int mt = 0; mt < 2; mt++) {
            #pragma unroll
            for (int h = 0; h < 2; h++) {
                const float s00 = S[mt][0][2*h], s01 = S[mt][0][2*h+1];
                const float s10 = S[mt][1][2*h], s11 = S[mt][1][2*h+1];
                float mx = fmaxf(fmaxf(s00, s01), fmaxf(s10, s11));
                mx = fmaxf(mx, __shfl_xor_sync(0xffffffffu, mx, 1));
                mx = fmaxf(mx, __shfl_xor_sync(0xffffffffu, mx, 2));
                const float mnew = fmaxf(Mx[mt][h], mx);
                const float sc = __expf(Mx[mt][h] - mnew);
                const float p00 = __expf(s00 - mnew), p01 = __expf(s01 - mnew);
                const float p10 = __expf(s10 - mnew), p11 = __expf(s11 - mnew);
                float sm = p00 + p01 + p10 + p11;
                sm += __shfl_xor_sync(0xffffffffu, sm, 1);
                sm += __shfl_xor_sync(0xffffffffu, sm, 2);
                Ls[mt][h] = Ls[mt][h] * sc + sm;
                Mx[mt][h] = mnew;
                #pragma unroll
                for (int dn = 0; dn < 8; dn++) {
                    O[mt][dn][2*h]   *= sc;
                    O[mt][dn][2*h+1] *= sc;
                }
                pa[mt][h]     = pack_h2(p00, p01);
                pa[mt][2 + h] = pack_h2(p10, p11);
            }
        }

        #pragma unroll
        for (int db = 0; db < 4; db++) {
            uint32_t vb[4];
            const uint32_t rv = (s * 16 * APITCH + db * 16) * 2;
            LDSM4T(vb[0], vb[1], vb[2], vb[3], vh_base + rv + v_off);
            #pragma unroll
            for (int mt = 0; mt < 2; mt++) {
                MMAH(O[mt][db * 2],     pa[mt], vb);
                MMAH(O[mt][db * 2 + 1], pa[mt], vb + 2);
            }
        }
    }

    const float sink = sinks[hkv * 8 + w];
    float rinv[2][2];
    #pragma unroll
    for (int mt = 0; mt < 2; mt++)
        #pragma unroll
        for (int h = 0; h < 2; h++)
            rinv[mt][h] = 1.0f / (Ls[mt][h] + __expf(sink - Mx[mt][h]));

    const int colb = (hkv * 8 + w) * 64 + col_l;
    #pragma unroll
    for (int mt = 0; mt < 2; mt++) {
        #pragma unroll
        for (int dn = 0; dn < 8; dn++) {
            #pragma unroll
            for (int h = 0; h < 2; h++) {
                const int q = q0 + mt * 16 + row_l + h * 8;
                const float v0 = O[mt][dn][2*h]   * rinv[mt][h];
                const float v1 = O[mt][dn][2*h+1] * rinv[mt][h];
                const __nv_bfloat16 h0 = __float2bfloat16(v0);
                const __nv_bfloat16 h1 = __float2bfloat16(v1);
                const size_t oi = (size_t)q * (NH * HD) + colb + dn * 8;
                *(__nv_bfloat162*)&ahi[oi] = __nv_bfloat162(h0, h1);
                *(__nv_bfloat162*)&alo[oi] = __nv_bfloat162(
                    __float2bfloat16(v0 - __bfloat162float(h0)),
                    __float2bfloat16(v1 - __bfloat162float(h1)));
            }
        }
    }
}

// ---------------------------------------------------------------------------
extern "C" void kernel_launch(void* const* d_in, const int* in_sizes, int n_in,
                              void* d_out, int out_size)
{
    (void)in_sizes; (void)n_in; (void)out_size;
    const float* x     = (const float*)d_in[0];
    const float* Wqkv  = (const float*)d_in[1];
    const float* bqkv  = (const float*)d_in[2];
    const float* Wout  = (const float*)d_in[3];
    const float* bout  = (const float*)d_in[4];
    const float* sinks = (const float*)d_in[5];
    float* out = (float*)d_out;

    void *p;
    cudaGetSymbolAddress(&p, g_qkv);  float* qkv = (float*)p;
    cudaGetSymbolAddress(&p, g_xq1);  signed char* xq1 = (signed char*)p;
    cudaGetSymbolAddress(&p, g_xq0);  signed char* xq0 = (signed char*)p;
    cudaGetSymbolAddress(&p, g_w1q1); signed char* w1q1 = (signed char*)p;
    cudaGetSymbolAddress(&p, g_w1q0); signed char* w1q0 = (signed char*)p;
    cudaGetSymbolAddress(&p, g_w2hi); __nv_bfloat16* w2hi = (__nv_bfloat16*)p;
    cudaGetSymbolAddress(&p, g_w2lo); __nv_bfloat16* w2lo = (__nv_bfloat16*)p;
    cudaGetSymbolAddress(&p, g_ahi);  __nv_bfloat16* ahi = (__nv_bfloat16*)p;
    cudaGetSymbolAddress(&p, g_alo);  __nv_bfloat16* alo = (__nv_bfloat16*)p;

    cudaFuncSetAttribute(gemm_imma,    cudaFuncAttributeMaxDynamicSharedMemorySize, GEMM_SMEM);
    cudaFuncSetAttribute(gemm_hmma<1>, cudaFuncAttributeMaxDynamicSharedMemorySize, GEMM_SMEM);
    cudaFuncSetAttribute(attn_mma,     cudaFuncAttributeMaxDynamicSharedMemorySize, ATTN_SMEM);

    // operand prep
    quant8<<<(T_SEQ * DMODEL + 255) / 256, 256>>>(x, xq1, xq0, T_SEQ * DMODEL, INV_DX);
    transpose_quant8<<<dim3(QKVD / 32, DMODEL / 32), dim3(32, 8)>>>(DMODEL, QKVD, Wqkv, w1q1, w1q0, INV_DW);
    transpose_convert<<<dim3(N2PAD / 32, (NH * HD) / 32), dim3(32, 8)>>>(NH * HD, DMODEL, Wout, w2hi, w2lo);

    // 1) qkv = x @ W_qkv + b_qkv   (int8 2-digit IMMA, 1536x5120x2880)
    gemm_imma<<<dim3(QKVD / 128, T_SEQ / 128), 512, GEMM_SMEM>>>(
        T_SEQ, QKVD, DMODEL, xq1, xq0, w1q1, w1q0, bqkv, qkv);

    // 2) RoPE
    rope_init<<<1, 32>>>();
    rope_kernel<<<(T_SEQ * 72 * 32) / 256, 256>>>(qkv);

    // 3) tensor-core attention (emits bf16 hi/lo directly)
    attn_mma<<<dim3(T_SEQ / QB, NKV), 256, ATTN_SMEM>>>(qkv, sinks, ahi, alo);

    // 4) out = att @ W_out + b_out (bf16 HMMA, 1536x2880x4096, N guarded)
    gemm_hmma<1><<<dim3(N2PAD / 128, T_SEQ / 128), 256, GEMM_SMEM>>>(
        T_SEQ, DMODEL, NH * HD, ahi, alo, w2hi, w2lo, bout, out);
}

// round 15
// speedup vs baseline: 2.2987x; 2.2987x over previous
#include <cuda_runtime.h>
#include <cuda_bf16.h>
#include <cuda_fp16.h>
#include <math.h>
#include <stdint.h>

#define T_SEQ   1536
#define DMODEL  2880
#define QKVD    5120
#define NH      64
#define NKV     8
#define HD      64
#define WIN     128
#define NEG_INF -1e30f
#define N2PAD   2944

// ---------------------------------------------------------------------------
// scratch
// ---------------------------------------------------------------------------
__device__ __align__(16) float g_qkv[T_SEQ * QKVD];
__device__ __align__(16) __nv_bfloat16 g_xhi[T_SEQ * DMODEL];
__device__ __align__(16) __nv_bfloat16 g_xlo[T_SEQ * DMODEL];
__device__ __align__(16) __nv_bfloat16 g_w1hi[QKVD * DMODEL];     // [N=5120, K=2880]
__device__ __align__(16) __nv_bfloat16 g_w1lo[QKVD * DMODEL];
__device__ __align__(16) __half g_w2h[N2PAD * (NH * HD)];         // [N, K=4096] fp16
__device__ __align__(16) __half g_ah[T_SEQ * NH * HD];            // attention out fp16
__device__ float g_invf[32];
__device__ float g_conc;

// ---------------------------------------------------------------------------
// PTX helpers (family-generic sm_80+ only)
// ---------------------------------------------------------------------------
__device__ __forceinline__ uint32_t smem_u32(const void* p) {
    uint32_t a;
    asm("{ .reg .u64 t; cvta.to.shared.u64 t, %1; cvt.u32.u64 %0, t; }" : "=r"(a) : "l"(p));
    return a;
}
#define CP_ASYNC16(dst, src) \
    asm volatile("cp.async.cg.shared.global [%0], [%1], 16;" :: "r"(dst), "l"(src))
#define CP_COMMIT() asm volatile("cp.async.commit_group;" ::: "memory")
#define CP_WAIT(n)  asm volatile("cp.async.wait_group %0;" :: "n"(n) : "memory")
#define LDSM4(r0, r1, r2, r3, addr) \
    asm volatile("ldmatrix.sync.aligned.m8n8.x4.shared.b16 {%0,%1,%2,%3}, [%4];" \
        : "=r"(r0), "=r"(r1), "=r"(r2), "=r"(r3) : "r"(addr))
#define LDSM4T(r0, r1, r2, r3, addr) \
    asm volatile("ldmatrix.sync.aligned.m8n8.x4.trans.shared.b16 {%0,%1,%2,%3}, [%4];" \
        : "=r"(r0), "=r"(r1), "=r"(r2), "=r"(r3) : "r"(addr))
#define MMA16816(d, a, b) \
    asm volatile("mma.sync.aligned.m16n8k16.row.col.f32.bf16.bf16.f32 " \
        "{%0,%1,%2,%3}, {%4,%5,%6,%7}, {%8,%9}, {%0,%1,%2,%3};" \
        : "+f"((d)[0]), "+f"((d)[1]), "+f"((d)[2]), "+f"((d)[3]) \
        : "r"((a)[0]), "r"((a)[1]), "r"((a)[2]), "r"((a)[3]), "r"((b)[0]), "r"((b)[1]))
#define MMAH(d, a, b) \
    asm volatile("mma.sync.aligned.m16n8k16.row.col.f32.f16.f16.f32 " \
        "{%0,%1,%2,%3}, {%4,%5,%6,%7}, {%8,%9}, {%0,%1,%2,%3};" \
        : "+f"((d)[0]), "+f"((d)[1]), "+f"((d)[2]), "+f"((d)[3]) \
        : "r"((a)[0]), "r"((a)[1]), "r"((a)[2]), "r"((a)[3]), "r"((b)[0]), "r"((b)[1]))

__device__ __forceinline__ uint32_t pack_h2(float a, float b) {
    __half2 h = __floats2half2_rn(a, b);
    return *(uint32_t*)&h;
}

// smem geometry: tiles of 128 rows x 80B pitch (64B data)
#define ROW_B   80
#define TILE_B  (128 * ROW_B)          // 10240
#define STAGE_B (4 * TILE_B)           // 40960 (GEMM1: Ahi Alo Bhi Blo)
#define GEMM_SMEM (2 * STAGE_B)        // 81920
#define STAGE2_B (2 * TILE_B)          // 20480 (GEMM2: A B)
#define GEMM2_SMEM (2 * STAGE2_B)      // 40960

// ---------------------------------------------------------------------------
// GEMM1: HMMA bf16-split (frozen since R6 — feeds softmax, precision-critical)
// ---------------------------------------------------------------------------
template <int GUARD_N>
__global__ __launch_bounds__(256, 2)
void gemm_hmma(int M, int N, int K,
               const __nv_bfloat16* __restrict__ Ahi, const __nv_bfloat16* __restrict__ Alo,
               const __nv_bfloat16* __restrict__ Bhi, const __nv_bfloat16* __restrict__ Blo,
               const float* __restrict__ bias, float* __restrict__ C)
{
    extern __shared__ char smem[];
    const uint32_t sb = smem_u32(smem);
    const int tid = threadIdx.x;
    const int wid = tid >> 5, lane = tid & 31;
    const int wm = wid & 1, wn = wid >> 1;          // 2 x 4 warp grid
    const int bm = blockIdx.y * 128, bn = blockIdx.x * 128;

    const int ld_row = tid >> 2;
    const int ld_c16 = tid & 3;
    const uint32_t ld_dst = sb + ld_row * ROW_B + ld_c16 * 16;
    const size_t a_off0 = (size_t)(bm + ld_row) * K + ld_c16 * 8;
    const size_t a_off1 = (size_t)(bm + ld_row + 64) * K + ld_c16 * 8;
    const size_t b_off0 = (size_t)(bn + ld_row) * K + ld_c16 * 8;
    const size_t b_off1 = (size_t)(bn + ld_row + 64) * K + ld_c16 * 8;

    const int a_row  = wm * 64 + (lane & 7) + (lane & 8);
    const int a_koff = ((lane >> 4) & 1) * 16;
    const int b_row  = wn * 32 + (lane & 7) + ((lane >> 4) & 1) * 8;
    const int b_koff = ((lane >> 3) & 1) * 16;

    float acc[4][4][4];
    #pragma unroll
    for (int i = 0; i < 4; i++)
        #pragma unroll
        for (int j = 0; j < 4; j++)
            #pragma unroll
            for (int r = 0; r < 4; r++) acc[i][j][r] = 0.0f;

    const int nch = K >> 5;

    auto load_stage = [&](int s, int c) {
        const uint32_t d0 = ld_dst + s * STAGE_B;
        const int kc = c * 32;
        CP_ASYNC16(d0 + 0 * TILE_B,              Ahi + a_off0 + kc);
        CP_ASYNC16(d0 + 0 * TILE_B + 64 * ROW_B, Ahi + a_off1 + kc);
        CP_ASYNC16(d0 + 1 * TILE_B,              Alo + a_off0 + kc);
        CP_ASYNC16(d0 + 1 * TILE_B + 64 * ROW_B, Alo + a_off1 + kc);
        CP_ASYNC16(d0 + 2 * TILE_B,              Bhi + b_off0 + kc);
        CP_ASYNC16(d0 + 2 * TILE_B + 64 * ROW_B, Bhi + b_off1 + kc);
        CP_ASYNC16(d0 + 3 * TILE_B,              Blo + b_off0 + kc);
        CP_ASYNC16(d0 + 3 * TILE_B + 64 * ROW_B, Blo + b_off1 + kc);
    };

    load_stage(0, 0);
    CP_COMMIT();

    for (int c = 0; c < nch; c++) {
        const int s = c & 1;
        CP_WAIT(0);
        __syncthreads();
        if (c + 1 < nch) {
            load_stage(s ^ 1, c + 1);
            CP_COMMIT();
        }

        const uint32_t stg = sb + s * STAGE_B;
        #pragma unroll
        for (int kk = 0; kk < 2; kk++) {
            const uint32_t a_k = a_koff + kk * 32;
            const uint32_t b_k = b_koff + kk * 32;
            uint32_t bh[4][2], bl[4][2];
            #pragma unroll
            for (int bp = 0; bp < 2; bp++) {
                const uint32_t rb = stg + 2 * TILE_B + (b_row + bp * 16) * ROW_B + b_k;
                LDSM4(bh[bp*2][0], bh[bp*2][1], bh[bp*2+1][0], bh[bp*2+1][1], rb);
                LDSM4(bl[bp*2][0], bl[bp*2][1], bl[bp*2+1][0], bl[bp*2+1][1], rb + TILE_B);
            }
            #pragma unroll
            for (int tm = 0; tm < 4; tm++) {
                uint32_t ah[4], al[4];
                const uint32_t ra = stg + (a_row + tm * 16) * ROW_B + a_k;
                LDSM4(ah[0], ah[1], ah[2], ah[3], ra);
                LDSM4(al[0], al[1], al[2], al[3], ra + TILE_B);
                #pragma unroll
                for (int tn = 0; tn < 4; tn++) MMA16816(acc[tm][tn], ah, bh[tn]);
                #pragma unroll
                for (int tn = 0; tn < 4; tn++) MMA16816(acc[tm][tn], ah, bl[tn]);
                #pragma unroll
                for (int tn = 0; tn < 4; tn++) MMA16816(acc[tm][tn], al, bh[tn]);
            }
        }
    }

    const int r_base = bm + wm * 64 + (lane >> 2);
    const int c_base = bn + wn * 32 + (lane & 3) * 2;
    #pragma unroll
    for (int tm = 0; tm < 4; tm++) {
        #pragma unroll
        for (int tn = 0; tn < 4; tn++) {
            const int cc = c_base + tn * 8;
            if (GUARD_N && cc >= N) continue;
            const float2 bs = *(const float2*)&bias[cc];
            const int r0 = r_base + tm * 16;
            float2 v0, v1;
            v0.x = acc[tm][tn][0] + bs.x; v0.y = acc[tm][tn][1] + bs.y;
            v1.x = acc[tm][tn][2] + bs.x; v1.y = acc[tm][tn][3] + bs.y;
            *(float2*)&C[(size_t)r0 * N + cc]       = v0;
            *(float2*)&C[(size_t)(r0 + 8) * N + cc] = v1;
        }
    }
}

// ---------------------------------------------------------------------------
// GEMM2: single-product fp16 HMMA. C = A[M,K] @ B[N,K]^T + bias (fp32 out).
// Error budget: A, B each rounded to fp16 (2^-12, 2^-12); no softmax
// amplification downstream. 3x fewer MMAs than the split GEMM.
// ---------------------------------------------------------------------------
template <int GUARD_N>
__global__ __launch_bounds__(256, 2)
void gemm_f16(int M, int N, int K,
              const __half* __restrict__ A, const __half* __restrict__ B,
              const float* __restrict__ bias, float* __restrict__ C)
{
    extern __shared__ char smem[];
    const uint32_t sb = smem_u32(smem);
    const int tid = threadIdx.x;
    const int wid = tid >> 5, lane = tid & 31;
    const int wm = wid & 1, wn = wid >> 1;
    const int bm = blockIdx.y * 128, bn = blockIdx.x * 128;

    const int ld_row = tid >> 2;
    const int ld_c16 = tid & 3;
    const uint32_t ld_dst = sb + ld_row * ROW_B + ld_c16 * 16;
    const size_t a_off0 = (size_t)(bm + ld_row) * K + ld_c16 * 8;
    const size_t a_off1 = (size_t)(bm + ld_row + 64) * K + ld_c16 * 8;
    const size_t b_off0 = (size_t)(bn + ld_row) * K + ld_c16 * 8;
    const size_t b_off1 = (size_t)(bn + ld_row + 64) * K + ld_c16 * 8;

    const int a_row  = wm * 64 + (lane & 7) + (lane & 8);
    const int a_koff = ((lane >> 4) & 1) * 16;
    const int b_row  = wn * 32 + (lane & 7) + ((lane >> 4) & 1) * 8;
    const int b_koff = ((lane >> 3) & 1) * 16;

    float acc[4][4][4];
    #pragma unroll
    for (int i = 0; i < 4; i++)
        #pragma unroll
        for (int j = 0; j < 4; j++)
            #pragma unroll
            for (int r = 0; r < 4; r++) acc[i][j][r] = 0.0f;

    const int nch = K >> 5;

    auto load_stage = [&](int s, int c) {
        const uint32_t d0 = ld_dst + s * STAGE2_B;
        const int kc = c * 32;
        CP_ASYNC16(d0,                           A + a_off0 + kc);
        CP_ASYNC16(d0 + 64 * ROW_B,              A + a_off1 + kc);
        CP_ASYNC16(d0 + TILE_B,                  B + b_off0 + kc);
        CP_ASYNC16(d0 + TILE_B + 64 * ROW_B,     B + b_off1 + kc);
    };

    load_stage(0, 0);
    CP_COMMIT();

    for (int c = 0; c < nch; c++) {
        const int s = c & 1;
        CP_WAIT(0);
        __syncthreads();
        if (c + 1 < nch) {
            load_stage(s ^ 1, c + 1);
            CP_COMMIT();
        }

        const uint32_t stg = sb + s * STAGE2_B;
        #pragma unroll
        for (int kk = 0; kk < 2; kk++) {
            const uint32_t a_k = a_koff + kk * 32;
            const uint32_t b_k = b_koff + kk * 32;
            uint32_t bh[4][2];
            #pragma unroll
            for (int bp = 0; bp < 2; bp++) {
                const uint32_t rb = stg + TILE_B + (b_row + bp * 16) * ROW_B + b_k;
                LDSM4(bh[bp*2][0], bh[bp*2][1], bh[bp*2+1][0], bh[bp*2+1][1], rb);
            }
            #pragma unroll
            for (int tm = 0; tm < 4; tm++) {
                uint32_t ah[4];
                const uint32_t ra = stg + (a_row + tm * 16) * ROW_B + a_k;
                LDSM4(ah[0], ah[1], ah[2], ah[3], ra);
                #pragma unroll
                for (int tn = 0; tn < 4; tn++) MMAH(acc[tm][tn], ah, bh[tn]);
            }
        }
    }

    const int r_base = bm + wm * 64 + (lane >> 2);
    const int c_base = bn + wn * 32 + (lane & 3) * 2;
    #pragma unroll
    for (int tm = 0; tm < 4; tm++) {
        #pragma unroll
        for (int tn = 0; tn < 4; tn++) {
            const int cc = c_base + tn * 8;
            if (GUARD_N && cc >= N) continue;
            const float2 bs = *(const float2*)&bias[cc];
            const int r0 = r_base + tm * 16;
            float2 v0, v1;
            v0.x = acc[tm][tn][0] + bs.x; v0.y = acc[tm][tn][1] + bs.y;
            v1.x = acc[tm][tn][2] + bs.x; v1.y = acc[tm][tn][3] + bs.y;
            *(float2*)&C[(size_t)r0 * N + cc]       = v0;
            *(float2*)&C[(size_t)(r0 + 8) * N + cc] = v1;
        }
    }
}

// ---------------------------------------------------------------------------
// fp32 -> bf16 hi/lo split (GEMM1 A operand)
// ---------------------------------------------------------------------------
__global__ void convert_hilo(const float* __restrict__ in,
                             __nv_bfloat16* __restrict__ hi,
                             __nv_bfloat16* __restrict__ lo, int n)
{
    int i = blockIdx.x * blockDim.x + threadIdx.x;
    if (i >= n) return;
    float v = in[i];
    __nv_bfloat16 h = __float2bfloat16(v);
    hi[i] = h;
    lo[i] = __float2bfloat16(v - __bfloat162float(h));
}

// ---------------------------------------------------------------------------
// W [K,N] fp32 -> Thi/Tlo [Npad,K] bf16 (GEMM1 weights)
// ---------------------------------------------------------------------------
__global__ void transpose_convert(int K, int N, const float* __restrict__ W,
                                  __nv_bfloat16* __restrict__ Thi,
                                  __nv_bfloat16* __restrict__ Tlo)
{
    __shared__ float tile[32][33];
    const int k0 = blockIdx.y * 32, n0 = blockIdx.x * 32;
    const int tx = threadIdx.x, ty = threadIdx.y;
    #pragma unroll
    for (int i = 0; i < 32; i += 8) {
        const int k = k0 + ty + i;
        tile[ty + i][tx] = (n0 + tx < N) ? W[(size_t)k * N + n0 + tx] : 0.0f;
    }
    __syncthreads();
    #pragma unroll
    for (int i = 0; i < 32; i += 8) {
        const int n = n0 + ty + i;
        const float v = (n < N) ? tile[tx][ty + i] : 0.0f;
        const __nv_bfloat16 h = __float2bfloat16(v);
        Thi[(size_t)n * K + k0 + tx] = h;
        Tlo[(size_t)n * K + k0 + tx] = __float2bfloat16(v - __bfloat162float(h));
    }
}

// ---------------------------------------------------------------------------
// W [K,N] fp32 -> T [Npad,K] fp16 single (GEMM2 weights)
// ---------------------------------------------------------------------------
__global__ void transpose_convert_f16(int K, int N, const float* __restrict__ W,
                                      __half* __restrict__ T)
{
    __shared__ float tile[32][33];
    const int k0 = blockIdx.y * 32, n0 = blockIdx.x * 32;
    const int tx = threadIdx.x, ty = threadIdx.y;
    #pragma unroll
    for (int i = 0; i < 32; i += 8) {
        const int k = k0 + ty + i;
        tile[ty + i][tx] = (n0 + tx < N) ? W[(size_t)k * N + n0 + tx] : 0.0f;
    }
    __syncthreads();
    #pragma unroll
    for (int i = 0; i < 32; i += 8) {
        const int n = n0 + ty + i;
        const float v = (n < N) ? tile[tx][ty + i] : 0.0f;
        T[(size_t)n * K + k0 + tx] = __float2half_rn(v);
    }
}

// ---------------------------------------------------------------------------
// YaRN RoPE
// ---------------------------------------------------------------------------
__global__ void rope_init()
{
    const int i = threadIdx.x;
    const double TWO_PI = 6.283185307179586;
    double freq = pow(150000.0, (double)(2 * i) / 64.0);
    double conc = 0.1 * log(32.0) + 1.0;
    double lo   = 32.0 * log(1024.0 / (32.0 * TWO_PI)) / log(150000.0);
    double hi   = 32.0 * log(1024.0 / TWO_PI) / log(150000.0);
    double ramp = ((double)i - lo) / (hi - lo);
    ramp = fmin(1.0, fmax(0.0, ramp));
    g_invf[i] = (float)(ramp / (32.0 * freq) + (1.0 - ramp) / freq);
    if (i == 0) g_conc = (float)conc;
}

__global__ void rope_kernel(float* __restrict__ qkv)
{
    const int gid = blockIdx.x * blockDim.x + threadIdx.x;
    const int i   = gid & 31;
    const int hh  = (gid >> 5) % 72;
    const int t   = gid / (32 * 72);
    if (t >= T_SEQ) return;

    const float ang = (float)t * g_invf[i];
    const float cc  = g_conc;
    const float c   = cosf(ang) * cc;
    const float s   = sinf(ang) * cc;

    const int col = (hh < 64) ? hh * 64 : 4096 + (hh - 64) * 64;
    float* p = qkv + (size_t)t * QKVD + col;
    const float x1 = p[i];
    const float x2 = p[i + 32];
    p[i]      = x1 * c - x2 * s;
    p[i + 32] = x2 * c + x1 * s;
}

// ---------------------------------------------------------------------------
// Tensor-core flash attention (R12 structure), output single fp16.
// ---------------------------------------------------------------------------
#define QB      32
#define KW      160
#define NSTRIP  10
#define APITCH  72
#define Q_BYTES (8 * QB * APITCH * 2)
#define K_BYTES (KW * APITCH * 2)
#define AOFF_QHI 0
#define AOFF_QLO (AOFF_QHI + Q_BYTES)
#define AOFF_KHI (AOFF_QLO + Q_BYTES)
#define AOFF_KLO (AOFF_KHI + K_BYTES)
#define AOFF_VH  (AOFF_KLO + K_BYTES)
#define ATTN_SMEM (AOFF_VH + K_BYTES)

__global__ __launch_bounds__(256)
void attn_mma(const float* __restrict__ qkv, const float* __restrict__ sinks,
              __half* __restrict__ aout)
{
    extern __shared__ char smem[];
    const uint32_t sb = smem_u32(smem);
    const int tid = threadIdx.x, lane = tid & 31, w = tid >> 5;
    const int qb = blockIdx.x, hkv = blockIdx.y;
    const int q0 = qb * QB;
    const int kbase = q0 - 128;

    __half* qh = (__half*)(smem + AOFF_QHI);
    __half* ql = (__half*)(smem + AOFF_QLO);
    __half* kh = (__half*)(smem + AOFF_KHI);
    __half* kl = (__half*)(smem + AOFF_KLO);
    __half* vh = (__half*)(smem + AOFF_VH);

    for (int idx = tid; idx < QB * 128; idx += 256) {
        const int q = idx >> 7, c4 = (idx & 127) << 2;
        const float4 v = *(const float4*)(qkv + (size_t)(q0 + q) * QKVD + hkv * 512 + c4);
        const int head = c4 >> 6, d = c4 & 63;
        __half* ph = qh + head * (QB * APITCH) + q * APITCH + d;
        __half* pl = ql + head * (QB * APITCH) + q * APITCH + d;
        const float a[4] = {v.x * 0.125f, v.y * 0.125f, v.z * 0.125f, v.w * 0.125f};
        #pragma unroll
        for (int t = 0; t < 4; t++) {
            const __half h = __float2half_rn(a[t]);
            ph[t] = h;
            pl[t] = __float2half_rn(a[t] - __half2float(h));
        }
    }
    for (int idx = tid; idx < KW * 16; idx += 256) {
        const int k = idx >> 4, c4 = (idx & 15) << 2;
        const int j = kbase + k;
        float4 kv = make_float4(0.f, 0.f, 0.f, 0.f);
        float4 vv = make_float4(0.f, 0.f, 0.f, 0.f);
        if (j >= 0) {
            kv = *(const float4*)(qkv + (size_t)j * QKVD + 4096 + hkv * 64 + c4);
            vv = *(const float4*)(qkv + (size_t)j * QKVD + 4608 + hkv * 64 + c4);
        }
        __half* pkh = kh + k * APITCH + c4;
        __half* pkl = kl + k * APITCH + c4;
        __half* pvh = vh + k * APITCH + c4;
        const float ka[4] = {kv.x, kv.y, kv.z, kv.w};
        const float va[4] = {vv.x, vv.y, vv.z, vv.w};
        #pragma unroll
        for (int t = 0; t < 4; t++) {
            const __half h = __float2half_rn(ka[t]);
            pkh[t] = h;
            pkl[t] = __float2half_rn(ka[t] - __half2float(h));
            pvh[t] = __float2half_rn(va[t]);
        }
    }
    __syncthreads();

    const uint32_t qhi_base = sb + AOFF_QHI + w * (QB * APITCH * 2);
    const uint32_t qlo_base = sb + AOFF_QLO + w * (QB * APITCH * 2);
    const uint32_t khi_base = sb + AOFF_KHI;
    const uint32_t klo_base = sb + AOFF_KLO;
    const uint32_t vh_base  = sb + AOFF_VH;

    const uint32_t a_off = ((lane & 15) * APITCH + (lane >> 4) * 8) * 2;
    const uint32_t k_off = (((lane & 7) + (lane >> 4) * 8) * APITCH + ((lane >> 3) & 1) * 8) * 2;
    const uint32_t v_off = (((lane & 7) + ((lane >> 3) & 1) * 8) * APITCH + (lane >> 4) * 8) * 2;

    float O[2][8][4];
    #pragma unroll
    for (int mt = 0; mt < 2; mt++)
        #pragma unroll
        for (int dn = 0; dn < 8; dn++)
            #pragma unroll
            for (int c = 0; c < 4; c++) O[mt][dn][c] = 0.0f;
    float Mx[2][2], Ls[2][2];
    #pragma unroll
    for (int mt = 0; mt < 2; mt++) { Mx[mt][0] = Mx[mt][1] = -50.0f; Ls[mt][0] = Ls[mt][1] = 0.0f; }

    const int row_l = lane >> 2;
    const int col_l = (lane & 3) << 1;

    int s0 = 0;
    if (kbase < 0) s0 = (-kbase) >> 4;

    for (int s = s0; s < NSTRIP; s++) {
        const int kg0 = kbase + s * 16;
        float S[2][2][4];
        #pragma unroll
        for (int mt = 0; mt < 2; mt++)
            #pragma unroll
            for (int nt = 0; nt < 2; nt++)
                #pragma unroll
                for (int c = 0; c < 4; c++) S[mt][nt][c] = 0.0f;

        #pragma unroll
        for (int kt = 0; kt < 4; kt++) {
            uint32_t kbh[4], kbl[4];
            const uint32_t rk = (s * 16 * APITCH + kt * 16) * 2;
            LDSM4(kbh[0], kbh[1], kbh[2], kbh[3], khi_base + rk + k_off);
            LDSM4(kbl[0], kbl[1], kbl[2], kbl[3], klo_base + rk + k_off);
            #pragma unroll
            for (int mt = 0; mt < 2; mt++) {
                uint32_t ah[4], al[4];
                const uint32_t rq = (mt * 16 * APITCH + kt * 16) * 2;
                LDSM4(ah[0], ah[1], ah[2], ah[3], qhi_base + rq + a_off);
                LDSM4(al[0], al[1], al[2], al[3], qlo_base + rq + a_off);
                #pragma unroll
                for (int nt = 0; nt < 2; nt++) {
                    MMAH(S[mt][nt], ah, kbh + nt * 2);
                    MMAH(S[mt][nt], ah, kbl + nt * 2);
                    MMAH(S[mt][nt], al, kbh + nt * 2);
                }
            }
        }

        #pragma unroll
        for (int mt = 0; mt < 2; mt++)
            #pragma unroll
            for (int nt = 0; nt < 2; nt++)
                #pragma unroll
                for (int c = 0; c < 4; c++) {
                    const int i = q0 + mt * 16 + row_l + ((c >> 1) << 3);
                    const int j = kg0 + nt * 8 + col_l + (c & 1);
                    const bool ok = (j >= 0) && (j <= i) && (j > i - WIN);
                    if (!ok) S[mt][nt][c] = NEG_INF;
                }

        uint32_t pa[2][4];
        #pragma unroll
        for (int mt = 0; mt < 2; mt++) {
            #pragma unroll
            for (int h = 0; h < 2; h++) {
                const float s00 = S[mt][0][2*h], s01 = S[mt][0][2*h+1];
                const float s10 = S[mt][1][2*h], s11 = S[mt][1][2*h+1];
                float mx = fmaxf(fmaxf(s00, s01), fmaxf(s10, s11));
                mx = fmaxf(mx, __shfl_xor_sync(0xffffffffu, mx, 1));
                mx = fmaxf(mx, __shfl_xor_sync(0xffffffffu, mx, 2));
                const float mnew = fmaxf(Mx[mt][h], mx);
                const float sc = __expf(Mx[mt][h] - mnew);
                const float p00 = __expf(s00 - mnew), p01 = __expf(s01 - mnew);
                const float p10 = __expf(s10 - mnew), p11 = __expf(s11 - mnew);
                float sm = p00 + p01 + p10 + p11;
                sm += __shfl_xor_sync(0xffffffffu, sm, 1);
                sm += __shfl_xor_sync(0xffffffffu, sm, 2);
                Ls[mt][h] = Ls[mt][h] * sc + sm;
                Mx[mt][h] = mnew;
                #pragma unroll
                for (int dn = 0; dn < 8; dn++) {
                    O[mt][dn][2*h]   *= sc;
                    O[mt][dn][2*h+1] *= sc;
                }
                pa[mt][h]     = pack_h2(p00, p01);
                pa[mt][2 + h] = pack_h2(p10, p11);
            }
        }

        #pragma unroll
        for (int db = 0; db < 4; db++) {
            uint32_t vb[4];
            const uint32_t rv = (s * 16 * APITCH + db * 16) * 2;
            LDSM4T(vb[0], vb[1], vb[2], vb[3], vh_base + rv + v_off);
            #pragma unroll
            for (int mt = 0; mt < 2; mt++) {
                MMAH(O[mt][db * 2],     pa[mt], vb);
                MMAH(O[mt][db * 2 + 1], pa[mt], vb + 2);
            }
        }
    }

    const float sink = sinks[hkv * 8 + w];
    float rinv[2][2];
    #pragma unroll
    for (int mt = 0; mt < 2; mt++)
        #pragma unroll
        for (int h = 0; h < 2; h++)
            rinv[mt][h] = 1.0f / (Ls[mt][h] + __expf(sink - Mx[mt][h]));

    const int colb = (hkv * 8 + w) * 64 + col_l;
    #pragma unroll
    for (int mt = 0; mt < 2; mt++) {
        #pragma unroll
        for (int dn = 0; dn < 8; dn++) {
            #pragma unroll
            for (int h = 0; h < 2; h++) {
                const int q = q0 + mt * 16 + row_l + h * 8;
                const float v0 = O[mt][dn][2*h]   * rinv[mt][h];
                const float v1 = O[mt][dn][2*h+1] * rinv[mt][h];
                const size_t oi = (size_t)q * (NH * HD) + colb + dn * 8;
                *(__half2*)&aout[oi] = __floats2half2_rn(v0, v1);
            }
        }
    }
}

// ---------------------------------------------------------------------------
extern "C" void kernel_launch(void* const* d_in, const int* in_sizes, int n_in,
                              void* d_out, int out_size)
{
    (void)in_sizes; (void)n_in; (void)out_size;
    const float* x     = (const float*)d_in[0];
    const float* Wqkv  = (const float*)d_in[1];
    const float* bqkv  = (const float*)d_in[2];
    const float* Wout  = (const float*)d_in[3];
    const float* bout  = (const float*)d_in[4];
    const float* sinks = (const float*)d_in[5];
    float* out = (float*)d_out;

    void *p;
    cudaGetSymbolAddress(&p, g_qkv);  float* qkv = (float*)p;
    cudaGetSymbolAddress(&p, g_xhi);  __nv_bfloat16* xhi = (__nv_bfloat16*)p;
    cudaGetSymbolAddress(&p, g_xlo);  __nv_bfloat16* xlo = (__nv_bfloat16*)p;
    cudaGetSymbolAddress(&p, g_w1hi); __nv_bfloat16* w1hi = (__nv_bfloat16*)p;
    cudaGetSymbolAddress(&p, g_w1lo); __nv_bfloat16* w1lo = (__nv_bfloat16*)p;
    cudaGetSymbolAddress(&p, g_w2h);  __half* w2h = (__half*)p;
    cudaGetSymbolAddress(&p, g_ah);   __half* ah = (__half*)p;

    cudaFuncSetAttribute(gemm_hmma<0>, cudaFuncAttributeMaxDynamicSharedMemorySize, GEMM_SMEM);
    cudaFuncSetAttribute(gemm_f16<1>,  cudaFuncAttributeMaxDynamicSharedMemorySize, GEMM2_SMEM);
    cudaFuncSetAttribute(attn_mma,     cudaFuncAttributeMaxDynamicSharedMemorySize, ATTN_SMEM);

    // operand prep
    convert_hilo<<<(T_SEQ * DMODEL + 255) / 256, 256>>>(x, xhi, xlo, T_SEQ * DMODEL);
    transpose_convert<<<dim3(QKVD / 32, DMODEL / 32), dim3(32, 8)>>>(DMODEL, QKVD, Wqkv, w1hi, w1lo);
    transpose_convert_f16<<<dim3(N2PAD / 32, (NH * HD) / 32), dim3(32, 8)>>>(NH * HD, DMODEL, Wout, w2h);

    // 1) qkv = x @ W_qkv + b_qkv   (bf16 3-product, 1536x5120x2880)
    gemm_hmma<0><<<dim3(QKVD / 128, T_SEQ / 128), 256, GEMM_SMEM>>>(
        T_SEQ, QKVD, DMODEL, xhi, xlo, w1hi, w1lo, bqkv, qkv);

    // 2) RoPE
    rope_init<<<1, 32>>>();
    rope_kernel<<<(T_SEQ * 72 * 32) / 256, 256>>>(qkv);

    // 3) tensor-core attention (emits fp16 directly)
    attn_mma<<<dim3(T_SEQ / QB, NKV), 256, ATTN_SMEM>>>(qkv, sinks, ah);

    // 4) out = att @ W_out + b_out (fp16 1-product, 1536x2880x4096, N guarded)
    gemm_f16<1><<<dim3(N2PAD / 128, T_SEQ / 128), 256, GEMM2_SMEM>>>(
        T_SEQ, DMODEL, NH * HD, ah, w2h, bout, out);
}